// round 3
// baseline (speedup 1.0000x reference)
#include <cuda_runtime.h>
#include <math.h>

// Tropical (max-plus) matmul, split-K + packed-FFMA2 version:
//   out[b,o] = max_i ( W[o,i] + X[b,i] * factors[o] )
// B=512, OUT=1024, IN=1024, fp32.
//
// ALU pipe (FMNMX, rt=2/SMSP) is the hardware floor (~55K cyc). FFMA runs
// at rt=1 so the FMA pipe has headroom; we use fma.rn.f32x2 (FFMA2) packed
// over the output dim to halve FFMA issue count and free issue slots so the
// FMNMX stream saturates its pipe. X is stored duplicated ({x,x} pairs) in
// smem so all f32x2 operands come 64b-aligned straight from LDS (no MOVs).

#define B_DIM   512
#define OUT_DIM 1024
#define IN_DIM  1024

#define BM 64
#define BN 128
#define BK 16
#define TM 8
#define TN 8
#define THREADS 128
#define KSPLIT 7
#define NKT (IN_DIM / BK)     // 64 k-tiles

#define XPAD 132              // 128 duplicated floats + 4 (16B-aligned rows)
#define WPAD 132              // 128 + 4

typedef unsigned long long u64;

__device__ float g_scratch[KSPLIT * B_DIM * OUT_DIM];

__device__ __forceinline__ u64 ffma2(u64 a, u64 b, u64 c) {
    u64 d;
    asm("fma.rn.f32x2 %0, %1, %2, %3;" : "=l"(d) : "l"(a), "l"(b), "l"(c));
    return d;
}
__device__ __forceinline__ float2 u2f2(u64 u) {
    float2 f;
    asm("mov.b64 {%0, %1}, %2;" : "=f"(f.x), "=f"(f.y) : "l"(u));
    return f;
}
__device__ __forceinline__ u64 f2u(float a, float b) {
    u64 u;
    asm("mov.b64 %0, {%1, %2};" : "=l"(u) : "f"(a), "f"(b));
    return u;
}

__global__ __launch_bounds__(THREADS, 3)
void scaled_maxplus_partial(const float* __restrict__ X,
                            const float* __restrict__ W,
                            const float* __restrict__ F)
{
    // Xs holds X duplicated: row k = {x0,x0,x1,x1,...,x63,x63}
    __shared__ float Xs[2][BK][XPAD];
    __shared__ float Ws[2][BK][WPAD];

    const int tid = threadIdx.x;
    const int tx  = tid & 15;   // n direction, 0..15 (8 cols each)
    const int ty  = tid >> 4;   // m direction, 0..7  (8 rows each)

    const int bm0 = blockIdx.y * BM;
    const int bn0 = blockIdx.x * BN;
    const int z   = blockIdx.z;

    const int t0 = (z * NKT) / KSPLIT;
    const int t1 = ((z + 1) * NKT) / KSPLIT;

    // loader mapping: 2 X float4 + 4 W float4 per thread per stage
    const int lrow = tid >> 2;          // 0..31
    const int lk4  = (tid & 3) << 2;    // 0,4,8,12

    const float4* __restrict__ Xg0 =
        reinterpret_cast<const float4*>(X + (size_t)(bm0 + lrow) * IN_DIM + lk4);
    const float4* __restrict__ Xg1 =
        reinterpret_cast<const float4*>(X + (size_t)(bm0 + lrow + 32) * IN_DIM + lk4);
    const float4* __restrict__ Wg0 =
        reinterpret_cast<const float4*>(W + (size_t)(bn0 + lrow) * IN_DIM + lk4);
    const float4* __restrict__ Wg1 =
        reinterpret_cast<const float4*>(W + (size_t)(bn0 + lrow + 32) * IN_DIM + lk4);
    const float4* __restrict__ Wg2 =
        reinterpret_cast<const float4*>(W + (size_t)(bn0 + lrow + 64) * IN_DIM + lk4);
    const float4* __restrict__ Wg3 =
        reinterpret_cast<const float4*>(W + (size_t)(bn0 + lrow + 96) * IN_DIM + lk4);

    // packed factor pairs {f_j, f_j+1}
    u64 fp[4];
    #pragma unroll
    for (int p = 0; p < 4; p++)
        fp[p] = f2u(F[bn0 + tx * TN + 2 * p], F[bn0 + tx * TN + 2 * p + 1]);

    float acc[TM][TN];
    #pragma unroll
    for (int i = 0; i < TM; i++)
        #pragma unroll
        for (int j = 0; j < TN; j++)
            acc[i][j] = -INFINITY;

    // ---- staging helper (duplicate X, plain W) done inline twice
    #define STAGE(S, XA, XB, WA, WB, WC, WD)                                   \
    do {                                                                       \
        *reinterpret_cast<float2*>(&Xs[S][lk4+0][2*lrow])      = make_float2((XA).x,(XA).x); \
        *reinterpret_cast<float2*>(&Xs[S][lk4+1][2*lrow])      = make_float2((XA).y,(XA).y); \
        *reinterpret_cast<float2*>(&Xs[S][lk4+2][2*lrow])      = make_float2((XA).z,(XA).z); \
        *reinterpret_cast<float2*>(&Xs[S][lk4+3][2*lrow])      = make_float2((XA).w,(XA).w); \
        *reinterpret_cast<float2*>(&Xs[S][lk4+0][2*(lrow+32)]) = make_float2((XB).x,(XB).x); \
        *reinterpret_cast<float2*>(&Xs[S][lk4+1][2*(lrow+32)]) = make_float2((XB).y,(XB).y); \
        *reinterpret_cast<float2*>(&Xs[S][lk4+2][2*(lrow+32)]) = make_float2((XB).z,(XB).z); \
        *reinterpret_cast<float2*>(&Xs[S][lk4+3][2*(lrow+32)]) = make_float2((XB).w,(XB).w); \
        Ws[S][lk4+0][lrow]    = (WA).x; Ws[S][lk4+1][lrow]    = (WA).y;        \
        Ws[S][lk4+2][lrow]    = (WA).z; Ws[S][lk4+3][lrow]    = (WA).w;        \
        Ws[S][lk4+0][lrow+32] = (WB).x; Ws[S][lk4+1][lrow+32] = (WB).y;        \
        Ws[S][lk4+2][lrow+32] = (WB).z; Ws[S][lk4+3][lrow+32] = (WB).w;        \
        Ws[S][lk4+0][lrow+64] = (WC).x; Ws[S][lk4+1][lrow+64] = (WC).y;        \
        Ws[S][lk4+2][lrow+64] = (WC).z; Ws[S][lk4+3][lrow+64] = (WC).w;        \
        Ws[S][lk4+0][lrow+96] = (WD).x; Ws[S][lk4+1][lrow+96] = (WD).y;        \
        Ws[S][lk4+2][lrow+96] = (WD).z; Ws[S][lk4+3][lrow+96] = (WD).w;        \
    } while (0)

    // prologue
    {
        const int off = t0 * (BK / 4);
        float4 xa = Xg0[off], xb = Xg1[off];
        float4 wa = Wg0[off], wb = Wg1[off], wc = Wg2[off], wd = Wg3[off];
        STAGE(0, xa, xb, wa, wb, wc, wd);
    }
    __syncthreads();

    int cur = 0;
    for (int t = t0; t < t1; t++) {
        float4 xa, xb, wa, wb, wc, wd;
        const bool more = (t + 1 < t1);
        if (more) {
            const int off = (t + 1) * (BK / 4);
            xa = Xg0[off]; xb = Xg1[off];
            wa = Wg0[off]; wb = Wg1[off]; wc = Wg2[off]; wd = Wg3[off];
        }

        #pragma unroll
        for (int k = 0; k < BK; k++) {
            const float* xrow = &Xs[cur][k][ty * 16];  // 8 dup-pairs = 64B
            const float* wrow = &Ws[cur][k][tx * 8];   // 4 pairs     = 32B

            u64 xp[8], wp[4];
            #pragma unroll
            for (int p = 0; p < 4; p++) {
                ulonglong2 v = *reinterpret_cast<const ulonglong2*>(xrow + p * 4);
                xp[2*p] = v.x; xp[2*p+1] = v.y;
            }
            #pragma unroll
            for (int p = 0; p < 2; p++) {
                ulonglong2 v = *reinterpret_cast<const ulonglong2*>(wrow + p * 4);
                wp[2*p] = v.x; wp[2*p+1] = v.y;
            }

            #pragma unroll
            for (int i = 0; i < TM; i++)
                #pragma unroll
                for (int jp = 0; jp < 4; jp++) {
                    float2 c = u2f2(ffma2(xp[i], fp[jp], wp[jp]));
                    acc[i][2*jp]   = fmaxf(acc[i][2*jp],   c.x);
                    acc[i][2*jp+1] = fmaxf(acc[i][2*jp+1], c.y);
                }
        }

        if (more) {
            const int nxt = cur ^ 1;
            STAGE(nxt, xa, xb, wa, wb, wc, wd);
            __syncthreads();
            cur = nxt;
        }
    }

    float* dst_base = g_scratch + (size_t)z * B_DIM * OUT_DIM;
    #pragma unroll
    for (int i = 0; i < TM; i++) {
        float* dst = dst_base + (size_t)(bm0 + ty * TM + i) * OUT_DIM + bn0 + tx * TN;
        *reinterpret_cast<float4*>(dst) =
            make_float4(acc[i][0], acc[i][1], acc[i][2], acc[i][3]);
        *reinterpret_cast<float4*>(dst + 4) =
            make_float4(acc[i][4], acc[i][5], acc[i][6], acc[i][7]);
    }
}

__global__ __launch_bounds__(256)
void maxreduce_splits(float* __restrict__ out)
{
    const int idx4 = blockIdx.x * blockDim.x + threadIdx.x;  // float4 index
    const int n4 = B_DIM * OUT_DIM / 4;
    if (idx4 >= n4) return;

    const float4* s = reinterpret_cast<const float4*>(g_scratch);
    float4 m = s[idx4];
    #pragma unroll
    for (int z = 1; z < KSPLIT; z++) {
        float4 v = s[(size_t)z * n4 + idx4];
        m.x = fmaxf(m.x, v.x);
        m.y = fmaxf(m.y, v.y);
        m.z = fmaxf(m.z, v.z);
        m.w = fmaxf(m.w, v.w);
    }
    reinterpret_cast<float4*>(out)[idx4] = m;
}

extern "C" void kernel_launch(void* const* d_in, const int* in_sizes, int n_in,
                              void* d_out, int out_size)
{
    const float* X = (const float*)d_in[0];   // (512, 1024)
    const float* W = (const float*)d_in[1];   // (1024, 1024)
    const float* F = (const float*)d_in[2];   // (1024, 1)
    float* out = (float*)d_out;               // (512, 1024)

    dim3 grid(OUT_DIM / BN, B_DIM / BM, KSPLIT);   // (8, 8, 7) = 448 CTAs
    scaled_maxplus_partial<<<grid, THREADS>>>(X, W, F);

    const int n4 = B_DIM * OUT_DIM / 4;            // 131072
    maxreduce_splits<<<(n4 + 255) / 256, 256>>>(out);
}

// round 5
// speedup vs baseline: 3.1263x; 3.1263x over previous
#include <cuda_runtime.h>
#include <math.h>

// Tropical (max-plus) matmul with exact candidate pruning:
//   out[b,o] = max_i ( W[o,i] + X[b,i] * factors[o] )
// B=512, OUT=1024, IN=1024, fp32.
//
// Key insight: for a positive factor f, the argmax i must satisfy
//   X[b,i] >= X_max[b] - (Whi_g - Wlo_g) / f_pos_min
// (any other i loses to the candidate at argmax X even with the most
// favorable W). With the dataset's xavier W (spread ~0.108) and N(0,1) X,
// this leaves ~1-3 candidates per batch row -> ~400x less max work.
// Symmetric bound with X_min covers f<0; f==0 and candidate-overflow fall
// back to exact dense scans, so the kernel is exact for ANY input.

#define B_DIM   512
#define OUT_DIM 1024
#define IN_DIM  1024
#define CAP     64

typedef unsigned int u32;

__device__ float g_WT[(size_t)IN_DIM * OUT_DIM];   // WT[i][o] = W[o][i]
__device__ u32   g_whi_key, g_wlo_key;             // ordered-uint encoded W min/max
__device__ float g_fposmin, g_fnegminabs;

__device__ int   g_cnt_pos[B_DIM], g_cnt_neg[B_DIM];
__device__ int   g_ci_pos[B_DIM][CAP];
__device__ float g_cx_pos[B_DIM][CAP];
__device__ int   g_ci_neg[B_DIM][CAP];
__device__ float g_cx_neg[B_DIM][CAP];

// monotone float <-> uint encoding (float order == unsigned order)
__device__ __forceinline__ u32 fenc(float f) {
    u32 u = __float_as_uint(f);
    return (u & 0x80000000u) ? ~u : (u | 0x80000000u);
}
__device__ __forceinline__ float fdec(u32 k) {
    u32 u = (k & 0x80000000u) ? (k & 0x7FFFFFFFu) : ~k;
    return __uint_as_float(u);
}

// ---------------- P0: init globals + factor statistics ----------------
__global__ void p0_init_fstats(const float* __restrict__ F)
{
    __shared__ float sp[256], sn[256];
    const int tid = threadIdx.x;
    if (tid == 0) { g_whi_key = 0u; g_wlo_key = 0xFFFFFFFFu; }

    float fp = INFINITY, fn = INFINITY;
    for (int o = tid; o < OUT_DIM; o += 256) {
        float f = F[o];
        if (f > 0.f) fp = fminf(fp, f);
        if (f < 0.f) fn = fminf(fn, -f);
    }
    sp[tid] = fp; sn[tid] = fn;
    __syncthreads();
    for (int s = 128; s > 0; s >>= 1) {
        if (tid < s) {
            sp[tid] = fminf(sp[tid], sp[tid + s]);
            sn[tid] = fminf(sn[tid], sn[tid + s]);
        }
        __syncthreads();
    }
    if (tid == 0) { g_fposmin = sp[0]; g_fnegminabs = sn[0]; }
}

// ---------------- P1: transpose W + global W min/max ----------------
__global__ __launch_bounds__(256)
void p1_transpose(const float* __restrict__ W)
{
    __shared__ float tile[32][33];
    __shared__ u32 shi[256], slo[256];

    const int tx = threadIdx.x;          // 0..31
    const int ty = threadIdx.y;          // 0..7
    const int tid = ty * 32 + tx;
    const int i0 = blockIdx.x * 32;      // input col (i)
    const int o0 = blockIdx.y * 32;      // input row (o)

    float lmax = -INFINITY, lmin = INFINITY;
    #pragma unroll
    for (int r = ty; r < 32; r += 8) {
        float v = W[(size_t)(o0 + r) * IN_DIM + i0 + tx];
        tile[r][tx] = v;
        lmax = fmaxf(lmax, v);
        lmin = fminf(lmin, v);
    }
    __syncthreads();
    #pragma unroll
    for (int r = ty; r < 32; r += 8)
        g_WT[(size_t)(i0 + r) * OUT_DIM + o0 + tx] = tile[tx][r];

    shi[tid] = fenc(lmax);
    slo[tid] = fenc(lmin);
    __syncthreads();
    for (int s = 128; s > 0; s >>= 1) {
        if (tid < s) {
            shi[tid] = max(shi[tid], shi[tid + s]);
            slo[tid] = min(slo[tid], slo[tid + s]);
        }
        __syncthreads();
    }
    if (tid == 0) {
        atomicMax(&g_whi_key, shi[0]);
        atomicMin(&g_wlo_key, slo[0]);
    }
}

// ---------------- P2: per-b row extrema + candidate lists ----------------
__global__ __launch_bounds__(256)
void p2_candidates(const float* __restrict__ X)
{
    __shared__ float smax[256], smin[256];
    __shared__ int cp, cn;

    const int b = blockIdx.x;
    const int tid = threadIdx.x;
    const float* xr = X + (size_t)b * IN_DIM;

    float v[4];
    float lmax = -INFINITY, lmin = INFINITY;
    #pragma unroll
    for (int j = 0; j < 4; j++) {
        v[j] = xr[tid + j * 256];
        lmax = fmaxf(lmax, v[j]);
        lmin = fminf(lmin, v[j]);
    }
    smax[tid] = lmax; smin[tid] = lmin;
    if (tid == 0) { cp = 0; cn = 0; }
    __syncthreads();
    for (int s = 128; s > 0; s >>= 1) {
        if (tid < s) {
            smax[tid] = fmaxf(smax[tid], smax[tid + s]);
            smin[tid] = fminf(smin[tid], smin[tid + s]);
        }
        __syncthreads();
    }
    const float xmax = smax[0], xmin = smin[0];
    const float spread = fdec(g_whi_key) - fdec(g_wlo_key);
    const float fpm = g_fposmin, fnm = g_fnegminabs;
    // inclusive (loosest-valid) thresholds; isinf -> no such factors
    const float tpos = isinf(fpm) ?  INFINITY : xmax - spread / fpm;
    const float tneg = isinf(fnm) ? -INFINITY : xmin + spread / fnm;

    #pragma unroll
    for (int j = 0; j < 4; j++) {
        if (v[j] >= tpos) {
            int slot = atomicAdd(&cp, 1);
            if (slot < CAP) {
                g_ci_pos[b][slot] = tid + j * 256;
                g_cx_pos[b][slot] = v[j];
            }
        }
        if (v[j] <= tneg) {
            int slot = atomicAdd(&cn, 1);
            if (slot < CAP) {
                g_ci_neg[b][slot] = tid + j * 256;
                g_cx_neg[b][slot] = v[j];
            }
        }
    }
    __syncthreads();
    if (tid == 0) { g_cnt_pos[b] = cp; g_cnt_neg[b] = cn; }
}

// ---------------- C: compute outputs from candidates ----------------
__global__ __launch_bounds__(1024)
void c_compute(const float* __restrict__ X,
               const float* __restrict__ F,
               float* __restrict__ out)
{
    __shared__ float s_cx[CAP], s_cnx[CAP];
    __shared__ int   s_ci[CAP], s_cni[CAP];
    __shared__ float s_xrow[IN_DIM];

    const int b = blockIdx.x;
    const int o = threadIdx.x;

    const int cp = g_cnt_pos[b];
    const int cn = g_cnt_neg[b];
    const bool fb_pos = cp > CAP;
    const bool fb_neg = cn > CAP;

    if (o < cp && o < CAP) { s_ci[o] = g_ci_pos[b][o]; s_cx[o]  = g_cx_pos[b][o]; }
    if (o < cn && o < CAP) { s_cni[o] = g_ci_neg[b][o]; s_cnx[o] = g_cx_neg[b][o]; }
    if (fb_pos || fb_neg)
        s_xrow[o] = X[(size_t)b * IN_DIM + o];
    __syncthreads();

    const float f = F[o];
    float acc = -INFINITY;

    if (f > 0.f) {
        if (!fb_pos) {
            for (int k = 0; k < cp; k++)
                acc = fmaxf(acc, fmaf(s_cx[k], f, g_WT[(size_t)s_ci[k] * OUT_DIM + o]));
        } else {
            for (int i = 0; i < IN_DIM; i++)
                acc = fmaxf(acc, fmaf(s_xrow[i], f, g_WT[(size_t)i * OUT_DIM + o]));
        }
    } else if (f < 0.f) {
        if (!fb_neg) {
            for (int k = 0; k < cn; k++)
                acc = fmaxf(acc, fmaf(s_cnx[k], f, g_WT[(size_t)s_cni[k] * OUT_DIM + o]));
        } else {
            for (int i = 0; i < IN_DIM; i++)
                acc = fmaxf(acc, fmaf(s_xrow[i], f, g_WT[(size_t)i * OUT_DIM + o]));
        }
    } else {
        // f == 0: out = max_i W[o,i], independent of X
        for (int i = 0; i < IN_DIM; i++)
            acc = fmaxf(acc, g_WT[(size_t)i * OUT_DIM + o]);
    }

    out[(size_t)b * OUT_DIM + o] = acc;
}

extern "C" void kernel_launch(void* const* d_in, const int* in_sizes, int n_in,
                              void* d_out, int out_size)
{
    const float* X = (const float*)d_in[0];   // (512, 1024)
    const float* W = (const float*)d_in[1];   // (1024, 1024)
    const float* F = (const float*)d_in[2];   // (1024, 1)
    float* out = (float*)d_out;               // (512, 1024)

    p0_init_fstats<<<1, 256>>>(F);

    dim3 tgrid(IN_DIM / 32, OUT_DIM / 32);    // 32 x 32 tiles
    dim3 tblk(32, 8);
    p1_transpose<<<tgrid, tblk>>>(W);

    p2_candidates<<<B_DIM, 256>>>(X);

    c_compute<<<B_DIM, 1024>>>(X, F, out);
}

// round 6
// speedup vs baseline: 3.3776x; 1.0804x over previous
#include <cuda_runtime.h>
#include <math.h>

// Tropical (max-plus) matmul with exact candidate pruning, 2-kernel version:
//   out[b,o] = max_i ( W[o,i] + X[b,i] * factors[o] )
// B=512, OUT=1024, IN=1024, fp32.
//
// For f>0 the argmax i must satisfy X[b,i] >= Xmax[b] - (Whi-Wlo)/f_pos_min
// (exact bound; ~1-3 survivors for N(0,1) X and xavier W). Symmetric bound
// for f<0; f==0 and overflow fall back to exact dense scans.
//
// Round 6: pipeline collapsed to 2 kernels. Stats kernel computes global W
// min/max (ordered-uint atomics; idempotent across graph replays) + factor
// stats, and warms L2 with W. Fused kernel (block per b) loads the X row,
// block-reduces max/min, builds candidate lists in smem, and computes the
// output row reading W row-major through L2 (no transpose needed).

#define B_DIM   512
#define OUT_DIM 1024
#define IN_DIM  1024
#define CAP     64

typedef unsigned int u32;

// ordered-uint encoded global W extrema; static init = valid bottom/top,
// atomics re-converge to the same values on every graph replay.
__device__ u32   g_whi_key = 0u;
__device__ u32   g_wlo_key = 0xFFFFFFFFu;
__device__ float g_fposmin, g_fnegminabs;

// monotone float <-> uint encoding (float order == unsigned order)
__device__ __forceinline__ u32 fenc(float f) {
    u32 u = __float_as_uint(f);
    return (u & 0x80000000u) ? ~u : (u | 0x80000000u);
}
__device__ __forceinline__ float fdec(u32 k) {
    u32 u = (k & 0x80000000u) ? (k & 0x7FFFFFFFu) : ~k;
    return __uint_as_float(u);
}

// ---------------- K1: W global min/max (+ F stats in block 0) -------------
__global__ __launch_bounds__(256)
void k_stats(const float* __restrict__ W, const float* __restrict__ F)
{
    __shared__ u32 shi[256], slo[256];
    __shared__ float sp[256], sn[256];

    const int tid = threadIdx.x;
    // each block covers 4096 floats of W via 4x float4 per thread
    const size_t base = (size_t)blockIdx.x * 4096 + tid * 4;

    float lmax = -INFINITY, lmin = INFINITY;
    #pragma unroll
    for (int j = 0; j < 4; j++) {
        float4 v = *reinterpret_cast<const float4*>(W + base + (size_t)j * 1024);
        lmax = fmaxf(fmaxf(fmaxf(lmax, v.x), fmaxf(v.y, v.z)), v.w);
        lmin = fminf(fminf(fminf(lmin, v.x), fminf(v.y, v.z)), v.w);
    }
    shi[tid] = fenc(lmax);
    slo[tid] = fenc(lmin);

    // block 0 also reduces factor stats
    float fp = INFINITY, fn = INFINITY;
    if (blockIdx.x == 0) {
        #pragma unroll
        for (int j = 0; j < 4; j++) {
            float f = F[tid + j * 256];
            if (f > 0.f) fp = fminf(fp, f);
            if (f < 0.f) fn = fminf(fn, -f);
        }
    }
    sp[tid] = fp; sn[tid] = fn;
    __syncthreads();

    for (int s = 128; s > 0; s >>= 1) {
        if (tid < s) {
            shi[tid] = max(shi[tid], shi[tid + s]);
            slo[tid] = min(slo[tid], slo[tid + s]);
            sp[tid]  = fminf(sp[tid], sp[tid + s]);
            sn[tid]  = fminf(sn[tid], sn[tid + s]);
        }
        __syncthreads();
    }
    if (tid == 0) {
        atomicMax(&g_whi_key, shi[0]);
        atomicMin(&g_wlo_key, slo[0]);
        if (blockIdx.x == 0) { g_fposmin = sp[0]; g_fnegminabs = sn[0]; }
    }
}

// ---------------- K2: fused candidates + compute (block per b) ------------
__global__ __launch_bounds__(1024, 2)
void k_fused(const float* __restrict__ X,
             const float* __restrict__ W,
             const float* __restrict__ F,
             float* __restrict__ out)
{
    __shared__ float s_x[IN_DIM];
    __shared__ float s_cx[CAP], s_cnx[CAP];
    __shared__ int   s_ci[CAP], s_cni[CAP];
    __shared__ int   cp_s, cn_s;
    __shared__ float rmax[32], rmin[32];
    __shared__ float xmax_s, xmin_s;

    const int b   = blockIdx.x;
    const int tid = threadIdx.x;
    const int lane = tid & 31;
    const int wid  = tid >> 5;

    const float v = X[(size_t)b * IN_DIM + tid];
    s_x[tid] = v;
    if (tid == 0) { cp_s = 0; cn_s = 0; }

    // block max/min reduction: warp shuffles -> smem -> warp 0
    float a = v, c = v;
    #pragma unroll
    for (int off = 16; off > 0; off >>= 1) {
        a = fmaxf(a, __shfl_xor_sync(0xFFFFFFFFu, a, off));
        c = fminf(c, __shfl_xor_sync(0xFFFFFFFFu, c, off));
    }
    if (lane == 0) { rmax[wid] = a; rmin[wid] = c; }
    __syncthreads();
    if (tid < 32) {
        float aa = rmax[tid], cc = rmin[tid];
        #pragma unroll
        for (int off = 16; off > 0; off >>= 1) {
            aa = fmaxf(aa, __shfl_xor_sync(0xFFFFFFFFu, aa, off));
            cc = fminf(cc, __shfl_xor_sync(0xFFFFFFFFu, cc, off));
        }
        if (tid == 0) { xmax_s = aa; xmin_s = cc; }
    }
    __syncthreads();

    // candidate thresholds (exact, inclusive)
    const float spread = fdec(g_whi_key) - fdec(g_wlo_key);
    const float fpm = g_fposmin, fnm = g_fnegminabs;
    const float tpos = isinf(fpm) ?  INFINITY : xmax_s - spread / fpm;
    const float tneg = isinf(fnm) ? -INFINITY : xmin_s + spread / fnm;

    if (v >= tpos) {
        int slot = atomicAdd(&cp_s, 1);
        if (slot < CAP) { s_ci[slot] = tid; s_cx[slot] = v; }
    }
    if (v <= tneg) {
        int slot = atomicAdd(&cn_s, 1);
        if (slot < CAP) { s_cni[slot] = tid; s_cnx[slot] = v; }
    }
    __syncthreads();

    const int cp = cp_s, cn = cn_s;
    const int o  = tid;
    const float f = F[o];
    const float* __restrict__ wrow = W + (size_t)o * IN_DIM;

    float acc = -INFINITY;

    if (f > 0.f && cp <= CAP) {
        // 4-wide batched gathers so L2 latencies overlap
        for (int k = 0; k < cp; k += 4) {
            float w0 = (k + 0 < cp) ? wrow[s_ci[k + 0]] : 0.f;
            float w1 = (k + 1 < cp) ? wrow[s_ci[k + 1]] : 0.f;
            float w2 = (k + 2 < cp) ? wrow[s_ci[k + 2]] : 0.f;
            float w3 = (k + 3 < cp) ? wrow[s_ci[k + 3]] : 0.f;
            float c0 = (k + 0 < cp) ? s_cx[k + 0] : -INFINITY;
            float c1 = (k + 1 < cp) ? s_cx[k + 1] : -INFINITY;
            float c2 = (k + 2 < cp) ? s_cx[k + 2] : -INFINITY;
            float c3 = (k + 3 < cp) ? s_cx[k + 3] : -INFINITY;
            acc = fmaxf(acc, fmaxf(fmaxf(fmaf(c0, f, w0), fmaf(c1, f, w1)),
                                   fmaxf(fmaf(c2, f, w2), fmaf(c3, f, w3))));
        }
    } else if (f < 0.f && cn <= CAP) {
        for (int k = 0; k < cn; k += 4) {
            float w0 = (k + 0 < cn) ? wrow[s_cni[k + 0]] : 0.f;
            float w1 = (k + 1 < cn) ? wrow[s_cni[k + 1]] : 0.f;
            float w2 = (k + 2 < cn) ? wrow[s_cni[k + 2]] : 0.f;
            float w3 = (k + 3 < cn) ? wrow[s_cni[k + 3]] : 0.f;
            float c0 = (k + 0 < cn) ? s_cnx[k + 0] : INFINITY;   // inf * f<0 = -inf
            float c1 = (k + 1 < cn) ? s_cnx[k + 1] : INFINITY;
            float c2 = (k + 2 < cn) ? s_cnx[k + 2] : INFINITY;
            float c3 = (k + 3 < cn) ? s_cnx[k + 3] : INFINITY;
            acc = fmaxf(acc, fmaxf(fmaxf(fmaf(c0, f, w0), fmaf(c1, f, w1)),
                                   fmaxf(fmaf(c2, f, w2), fmaf(c3, f, w3))));
        }
    } else {
        // exact dense fallback: f == 0, or candidate overflow
        for (int i = 0; i < IN_DIM; i++)
            acc = fmaxf(acc, fmaf(s_x[i], f, wrow[i]));
    }

    out[(size_t)b * OUT_DIM + o] = acc;
}

extern "C" void kernel_launch(void* const* d_in, const int* in_sizes, int n_in,
                              void* d_out, int out_size)
{
    const float* X = (const float*)d_in[0];   // (512, 1024)
    const float* W = (const float*)d_in[1];   // (1024, 1024)
    const float* F = (const float*)d_in[2];   // (1024, 1)
    float* out = (float*)d_out;               // (512, 1024)

    k_stats<<<IN_DIM * OUT_DIM / 4096, 256>>>(W, F);   // 256 blocks
    k_fused<<<B_DIM, 1024>>>(X, W, F, out);
}

// round 7
// speedup vs baseline: 4.1445x; 1.2271x over previous
#include <cuda_runtime.h>
#include <math.h>

// Tropical (max-plus) matmul with exact candidate pruning, 2-kernel version:
//   out[b,o] = max_i ( W[o,i] + X[b,i] * factors[o] )
// B=512, OUT=1024, IN=1024, fp32.
//
// For f>0 the argmax i must satisfy X[b,i] >= Xmax[b] - (Whi-Wlo)/f_pos_min
// (exact bound; ~1-3 survivors for N(0,1) X and xavier W). Symmetric bound
// for f<0; f==0 and overflow fall back to exact dense scans.
//
// Round 7: transpose restored but FUSED into the stats kernel (which reads
// all of W anyway). k_fused then gathers candidate rows from WT fully
// coalesced (consecutive o -> consecutive addresses), killing the 4KB-stride
// gather that made Round 6's fused kernel slow.

#define B_DIM   512
#define OUT_DIM 1024
#define IN_DIM  1024
#define CAP     64

typedef unsigned int u32;

__device__ float g_WT[(size_t)IN_DIM * OUT_DIM];   // WT[i][o] = W[o][i]
// ordered-uint encoded global W extrema; static init = valid bottom/top,
// atomics re-converge to identical values on every graph replay.
__device__ u32   g_whi_key = 0u;
__device__ u32   g_wlo_key = 0xFFFFFFFFu;
__device__ float g_fposmin, g_fnegminabs;

// monotone float <-> uint encoding (float order == unsigned order)
__device__ __forceinline__ u32 fenc(float f) {
    u32 u = __float_as_uint(f);
    return (u & 0x80000000u) ? ~u : (u | 0x80000000u);
}
__device__ __forceinline__ float fdec(u32 k) {
    u32 u = (k & 0x80000000u) ? (k & 0x7FFFFFFFu) : ~k;
    return __uint_as_float(u);
}

// ------- K1: W transpose + global min/max (+ F stats in block (0,0)) ------
__global__ __launch_bounds__(256)
void k_stats_t(const float* __restrict__ W, const float* __restrict__ F)
{
    __shared__ float tile[32][33];
    __shared__ u32 shi[256], slo[256];
    __shared__ float sp[256], sn[256];

    const int tx  = threadIdx.x;         // 0..31
    const int ty  = threadIdx.y;         // 0..7
    const int tid = ty * 32 + tx;
    const int i0  = blockIdx.x * 32;     // W column block (input dim)
    const int o0  = blockIdx.y * 32;     // W row block (output dim)

    float lmax = -INFINITY, lmin = INFINITY;
    #pragma unroll
    for (int r = ty; r < 32; r += 8) {
        float v = W[(size_t)(o0 + r) * IN_DIM + i0 + tx];
        tile[r][tx] = v;
        lmax = fmaxf(lmax, v);
        lmin = fminf(lmin, v);
    }
    shi[tid] = fenc(lmax);
    slo[tid] = fenc(lmin);

    // block (0,0) also reduces factor stats
    float fp = INFINITY, fn = INFINITY;
    if (blockIdx.x == 0 && blockIdx.y == 0) {
        #pragma unroll
        for (int j = 0; j < 4; j++) {
            float f = F[tid + j * 256];
            if (f > 0.f) fp = fminf(fp, f);
            if (f < 0.f) fn = fminf(fn, -f);
        }
    }
    sp[tid] = fp; sn[tid] = fn;
    __syncthreads();

    // write transposed tile (coalesced along o)
    #pragma unroll
    for (int r = ty; r < 32; r += 8)
        g_WT[(size_t)(i0 + r) * OUT_DIM + o0 + tx] = tile[tx][r];

    for (int s = 128; s > 0; s >>= 1) {
        if (tid < s) {
            shi[tid] = max(shi[tid], shi[tid + s]);
            slo[tid] = min(slo[tid], slo[tid + s]);
            sp[tid]  = fminf(sp[tid], sp[tid + s]);
            sn[tid]  = fminf(sn[tid], sn[tid + s]);
        }
        __syncthreads();
    }
    if (tid == 0) {
        atomicMax(&g_whi_key, shi[0]);
        atomicMin(&g_wlo_key, slo[0]);
        if (blockIdx.x == 0 && blockIdx.y == 0) {
            g_fposmin = sp[0]; g_fnegminabs = sn[0];
        }
    }
}

// ---------------- K2: fused candidates + compute (block per b) ------------
__global__ __launch_bounds__(1024, 2)
void k_fused(const float* __restrict__ X,
             const float* __restrict__ F,
             float* __restrict__ out)
{
    __shared__ float s_x[IN_DIM];
    __shared__ float s_cx[CAP], s_cnx[CAP];
    __shared__ int   s_ci[CAP], s_cni[CAP];
    __shared__ int   cp_s, cn_s;
    __shared__ float rmax[32], rmin[32];
    __shared__ float xmax_s, xmin_s;

    const int b    = blockIdx.x;
    const int tid  = threadIdx.x;
    const int lane = tid & 31;
    const int wid  = tid >> 5;

    const float v = X[(size_t)b * IN_DIM + tid];
    s_x[tid] = v;
    if (tid == 0) { cp_s = 0; cn_s = 0; }

    // block max/min reduction: warp shuffles -> smem -> warp 0
    float a = v, c = v;
    #pragma unroll
    for (int off = 16; off > 0; off >>= 1) {
        a = fmaxf(a, __shfl_xor_sync(0xFFFFFFFFu, a, off));
        c = fminf(c, __shfl_xor_sync(0xFFFFFFFFu, c, off));
    }
    if (lane == 0) { rmax[wid] = a; rmin[wid] = c; }
    __syncthreads();
    if (tid < 32) {
        float aa = rmax[tid], cc = rmin[tid];
        #pragma unroll
        for (int off = 16; off > 0; off >>= 1) {
            aa = fmaxf(aa, __shfl_xor_sync(0xFFFFFFFFu, aa, off));
            cc = fminf(cc, __shfl_xor_sync(0xFFFFFFFFu, cc, off));
        }
        if (tid == 0) { xmax_s = aa; xmin_s = cc; }
    }
    __syncthreads();

    // candidate thresholds (exact, inclusive)
    const float spread = fdec(g_whi_key) - fdec(g_wlo_key);
    const float fpm = g_fposmin, fnm = g_fnegminabs;
    const float tpos = isinf(fpm) ?  INFINITY : xmax_s - spread / fpm;
    const float tneg = isinf(fnm) ? -INFINITY : xmin_s + spread / fnm;

    if (v >= tpos) {
        int slot = atomicAdd(&cp_s, 1);
        if (slot < CAP) { s_ci[slot] = tid; s_cx[slot] = v; }
    }
    if (v <= tneg) {
        int slot = atomicAdd(&cn_s, 1);
        if (slot < CAP) { s_cni[slot] = tid; s_cnx[slot] = v; }
    }
    __syncthreads();

    const int cp = cp_s, cn = cn_s;
    const int o  = tid;
    const float f = F[o];

    float acc = -INFINITY;

    if (f > 0.f && cp <= CAP) {
        // coalesced gathers from WT: consecutive o -> consecutive addresses.
        // 4-wide predicated batches so L2 latencies overlap.
        for (int k = 0; k < cp; k += 4) {
            float w0 = (k + 0 < cp) ? g_WT[(size_t)s_ci[k + 0] * OUT_DIM + o] : 0.f;
            float w1 = (k + 1 < cp) ? g_WT[(size_t)s_ci[k + 1] * OUT_DIM + o] : 0.f;
            float w2 = (k + 2 < cp) ? g_WT[(size_t)s_ci[k + 2] * OUT_DIM + o] : 0.f;
            float w3 = (k + 3 < cp) ? g_WT[(size_t)s_ci[k + 3] * OUT_DIM + o] : 0.f;
            float c0 = (k + 0 < cp) ? s_cx[k + 0] : -INFINITY;
            float c1 = (k + 1 < cp) ? s_cx[k + 1] : -INFINITY;
            float c2 = (k + 2 < cp) ? s_cx[k + 2] : -INFINITY;
            float c3 = (k + 3 < cp) ? s_cx[k + 3] : -INFINITY;
            acc = fmaxf(acc, fmaxf(fmaxf(fmaf(c0, f, w0), fmaf(c1, f, w1)),
                                   fmaxf(fmaf(c2, f, w2), fmaf(c3, f, w3))));
        }
    } else if (f < 0.f && cn <= CAP) {
        for (int k = 0; k < cn; k += 4) {
            float w0 = (k + 0 < cn) ? g_WT[(size_t)s_cni[k + 0] * OUT_DIM + o] : 0.f;
            float w1 = (k + 1 < cn) ? g_WT[(size_t)s_cni[k + 1] * OUT_DIM + o] : 0.f;
            float w2 = (k + 2 < cn) ? g_WT[(size_t)s_cni[k + 2] * OUT_DIM + o] : 0.f;
            float w3 = (k + 3 < cn) ? g_WT[(size_t)s_cni[k + 3] * OUT_DIM + o] : 0.f;
            float c0 = (k + 0 < cn) ? s_cnx[k + 0] : INFINITY;   // inf * f<0 = -inf
            float c1 = (k + 1 < cn) ? s_cnx[k + 1] : INFINITY;
            float c2 = (k + 2 < cn) ? s_cnx[k + 2] : INFINITY;
            float c3 = (k + 3 < cn) ? s_cnx[k + 3] : INFINITY;
            acc = fmaxf(acc, fmaxf(fmaxf(fmaf(c0, f, w0), fmaf(c1, f, w1)),
                                   fmaxf(fmaf(c2, f, w2), fmaf(c3, f, w3))));
        }
    } else {
        // exact dense fallback (f == 0 or overflow) — also coalesced via WT
        for (int i = 0; i < IN_DIM; i++)
            acc = fmaxf(acc, fmaf(s_x[i], f, g_WT[(size_t)i * OUT_DIM + o]));
    }

    out[(size_t)b * OUT_DIM + o] = acc;
}

extern "C" void kernel_launch(void* const* d_in, const int* in_sizes, int n_in,
                              void* d_out, int out_size)
{
    const float* X = (const float*)d_in[0];   // (512, 1024)
    const float* W = (const float*)d_in[1];   // (1024, 1024)
    const float* F = (const float*)d_in[2];   // (1024, 1)
    float* out = (float*)d_out;               // (512, 1024)

    dim3 tgrid(IN_DIM / 32, OUT_DIM / 32);    // 32 x 32 = 1024 tiles
    dim3 tblk(32, 8);
    k_stats_t<<<tgrid, tblk>>>(W, F);

    k_fused<<<B_DIM, 1024>>>(X, F, out);
}

// round 8
// speedup vs baseline: 4.7057x; 1.1354x over previous
#include <cuda_runtime.h>
#include <math.h>

// Tropical (max-plus) matmul with exact candidate pruning, 2-kernel version:
//   out[b,o] = max_i ( W[o,i] + X[b,i] * factors[o] )
// B=512, OUT=1024, IN=1024, fp32.
//
// For f>0 the argmax i must satisfy X[b,i] >= Xmax[b] - (Whi-Wlo)/f_pos_min
// (exact; ~1-3 survivors for N(0,1) X / xavier W). Symmetric bound for f<0;
// f==0, mixed signs, and candidate overflow use exact fallback paths.
//
// Round 8: k_fused reshaped to 256 threads x 4 outputs/thread (float4 X
// loads, 8-warp reduction, 4-way ILP gathers) so all 512 blocks are
// co-resident in one wave instead of 1.68 waves of 1024-thread blocks.

#define B_DIM   512
#define OUT_DIM 1024
#define IN_DIM  1024
#define CAP     64
#define TPB     256

typedef unsigned int u32;

__device__ float g_WT[(size_t)IN_DIM * OUT_DIM];   // WT[i][o] = W[o][i]
// ordered-uint encoded global W extrema; static init = valid bottom/top,
// atomics re-converge to identical values on every graph replay.
__device__ u32   g_whi_key = 0u;
__device__ u32   g_wlo_key = 0xFFFFFFFFu;
__device__ float g_fposmin, g_fnegminabs;

__device__ __forceinline__ u32 fenc(float f) {
    u32 u = __float_as_uint(f);
    return (u & 0x80000000u) ? ~u : (u | 0x80000000u);
}
__device__ __forceinline__ float fdec(u32 k) {
    u32 u = (k & 0x80000000u) ? (k & 0x7FFFFFFFu) : ~k;
    return __uint_as_float(u);
}

// ------- K1: W transpose + global min/max (+ F stats in block (0,0)) ------
__global__ __launch_bounds__(256)
void k_stats_t(const float* __restrict__ W, const float* __restrict__ F)
{
    __shared__ float tile[32][33];
    __shared__ u32 shi[256], slo[256];
    __shared__ float sp[256], sn[256];

    const int tx  = threadIdx.x;         // 0..31
    const int ty  = threadIdx.y;         // 0..7
    const int tid = ty * 32 + tx;
    const int i0  = blockIdx.x * 32;
    const int o0  = blockIdx.y * 32;

    float lmax = -INFINITY, lmin = INFINITY;
    #pragma unroll
    for (int r = ty; r < 32; r += 8) {
        float v = W[(size_t)(o0 + r) * IN_DIM + i0 + tx];
        tile[r][tx] = v;
        lmax = fmaxf(lmax, v);
        lmin = fminf(lmin, v);
    }
    shi[tid] = fenc(lmax);
    slo[tid] = fenc(lmin);

    float fp = INFINITY, fn = INFINITY;
    if (blockIdx.x == 0 && blockIdx.y == 0) {
        #pragma unroll
        for (int j = 0; j < 4; j++) {
            float f = F[tid + j * 256];
            if (f > 0.f) fp = fminf(fp, f);
            if (f < 0.f) fn = fminf(fn, -f);
        }
    }
    sp[tid] = fp; sn[tid] = fn;
    __syncthreads();

    #pragma unroll
    for (int r = ty; r < 32; r += 8)
        g_WT[(size_t)(i0 + r) * OUT_DIM + o0 + tx] = tile[tx][r];

    for (int s = 128; s > 0; s >>= 1) {
        if (tid < s) {
            shi[tid] = max(shi[tid], shi[tid + s]);
            slo[tid] = min(slo[tid], slo[tid + s]);
            sp[tid]  = fminf(sp[tid], sp[tid + s]);
            sn[tid]  = fminf(sn[tid], sn[tid + s]);
        }
        __syncthreads();
    }
    if (tid == 0) {
        atomicMax(&g_whi_key, shi[0]);
        atomicMin(&g_wlo_key, slo[0]);
        if (blockIdx.x == 0 && blockIdx.y == 0) {
            g_fposmin = sp[0]; g_fnegminabs = sn[0];
        }
    }
}

// ------- K2: fused candidates + compute; 256 thr, 4 outputs/thread --------
__global__ __launch_bounds__(TPB)
void k_fused(const float* __restrict__ X,
             const float* __restrict__ F,
             float* __restrict__ out)
{
    __shared__ float s_x[IN_DIM];
    __shared__ float s_cx[CAP], s_cnx[CAP];
    __shared__ int   s_ci[CAP], s_cni[CAP];
    __shared__ int   cp_s, cn_s;
    __shared__ float rmax[8], rmin[8];
    __shared__ float xmax_s, xmin_s;

    const int b    = blockIdx.x;
    const int tid  = threadIdx.x;
    const int lane = tid & 31;
    const int wid  = tid >> 5;

    if (tid == 0) { cp_s = 0; cn_s = 0; }

    // load 4 X elements per thread (float4, coalesced)
    const float4 v4 = reinterpret_cast<const float4*>(X + (size_t)b * IN_DIM)[tid];
    reinterpret_cast<float4*>(s_x)[tid] = v4;

    float a = fmaxf(fmaxf(v4.x, v4.y), fmaxf(v4.z, v4.w));
    float c = fminf(fminf(v4.x, v4.y), fminf(v4.z, v4.w));
    #pragma unroll
    for (int off = 16; off > 0; off >>= 1) {
        a = fmaxf(a, __shfl_xor_sync(0xFFFFFFFFu, a, off));
        c = fminf(c, __shfl_xor_sync(0xFFFFFFFFu, c, off));
    }
    if (lane == 0) { rmax[wid] = a; rmin[wid] = c; }
    __syncthreads();
    if (tid < 32) {
        float aa = (tid < 8) ? rmax[tid] : -INFINITY;
        float cc = (tid < 8) ? rmin[tid] :  INFINITY;
        #pragma unroll
        for (int off = 4; off > 0; off >>= 1) {
            aa = fmaxf(aa, __shfl_xor_sync(0xFFFFFFFFu, aa, off));
            cc = fminf(cc, __shfl_xor_sync(0xFFFFFFFFu, cc, off));
        }
        if (tid == 0) { xmax_s = aa; xmin_s = cc; }
    }
    __syncthreads();

    // candidate thresholds (exact, inclusive)
    const float spread = fdec(g_whi_key) - fdec(g_wlo_key);
    const float fpm = g_fposmin, fnm = g_fnegminabs;
    const float tpos = isinf(fpm) ?  INFINITY : xmax_s - spread / fpm;
    const float tneg = isinf(fnm) ? -INFINITY : xmin_s + spread / fnm;

    const float xv[4] = {v4.x, v4.y, v4.z, v4.w};
    #pragma unroll
    for (int j = 0; j < 4; j++) {
        if (xv[j] >= tpos) {
            int slot = atomicAdd(&cp_s, 1);
            if (slot < CAP) { s_ci[slot] = 4 * tid + j; s_cx[slot] = xv[j]; }
        }
        if (xv[j] <= tneg) {
            int slot = atomicAdd(&cn_s, 1);
            if (slot < CAP) { s_cni[slot] = 4 * tid + j; s_cnx[slot] = xv[j]; }
        }
    }
    __syncthreads();

    const int cp = cp_s, cn = cn_s;
    const int o  = tid;                  // outputs o, o+256, o+512, o+768
    const float f0 = F[o];
    const float f1 = F[o + 256];
    const float f2 = F[o + 512];
    const float f3 = F[o + 768];

    float a0 = -INFINITY, a1 = -INFINITY, a2 = -INFINITY, a3 = -INFINITY;

    const bool allpos = (f0 > 0.f) & (f1 > 0.f) & (f2 > 0.f) & (f3 > 0.f);
    const bool allneg = (f0 < 0.f) & (f1 < 0.f) & (f2 < 0.f) & (f3 < 0.f);

    if (allpos && cp <= CAP) {
        // 4 independent coalesced gathers per candidate -> overlapped latency
        for (int k = 0; k < cp; k++) {
            const float cx = s_cx[k];
            const float* __restrict__ row = g_WT + (size_t)s_ci[k] * OUT_DIM;
            a0 = fmaxf(a0, fmaf(cx, f0, row[o]));
            a1 = fmaxf(a1, fmaf(cx, f1, row[o + 256]));
            a2 = fmaxf(a2, fmaf(cx, f2, row[o + 512]));
            a3 = fmaxf(a3, fmaf(cx, f3, row[o + 768]));
        }
    } else if (allneg && cn <= CAP) {
        for (int k = 0; k < cn; k++) {
            const float cx = s_cnx[k];
            const float* __restrict__ row = g_WT + (size_t)s_cni[k] * OUT_DIM;
            a0 = fmaxf(a0, fmaf(cx, f0, row[o]));
            a1 = fmaxf(a1, fmaf(cx, f1, row[o + 256]));
            a2 = fmaxf(a2, fmaf(cx, f2, row[o + 512]));
            a3 = fmaxf(a3, fmaf(cx, f3, row[o + 768]));
        }
    } else {
        // general exact path, per output: sign-chosen candidate list or
        // dense fallback (f == 0 or overflow). Coalesced via WT.
        float fj[4] = {f0, f1, f2, f3};
        float* aj[4] = {&a0, &a1, &a2, &a3};
        #pragma unroll
        for (int j = 0; j < 4; j++) {
            const int oj = o + j * 256;
            const float f = fj[j];
            float acc = -INFINITY;
            if (f > 0.f && cp <= CAP) {
                for (int k = 0; k < cp; k++)
                    acc = fmaxf(acc, fmaf(s_cx[k], f,
                                 g_WT[(size_t)s_ci[k] * OUT_DIM + oj]));
            } else if (f < 0.f && cn <= CAP) {
                for (int k = 0; k < cn; k++)
                    acc = fmaxf(acc, fmaf(s_cnx[k], f,
                                 g_WT[(size_t)s_cni[k] * OUT_DIM + oj]));
            } else {
                for (int i = 0; i < IN_DIM; i++)
                    acc = fmaxf(acc, fmaf(s_x[i], f,
                                 g_WT[(size_t)i * OUT_DIM + oj]));
            }
            *aj[j] = acc;
        }
    }

    float* orow = out + (size_t)b * OUT_DIM;
    orow[o]       = a0;
    orow[o + 256] = a1;
    orow[o + 512] = a2;
    orow[o + 768] = a3;
}

extern "C" void kernel_launch(void* const* d_in, const int* in_sizes, int n_in,
                              void* d_out, int out_size)
{
    const float* X = (const float*)d_in[0];   // (512, 1024)
    const float* W = (const float*)d_in[1];   // (1024, 1024)
    const float* F = (const float*)d_in[2];   // (1024, 1)
    float* out = (float*)d_out;               // (512, 1024)

    dim3 tgrid(IN_DIM / 32, OUT_DIM / 32);    // 32 x 32 = 1024 tiles
    dim3 tblk(32, 8);
    k_stats_t<<<tgrid, tblk>>>(W, F);

    k_fused<<<B_DIM, TPB>>>(X, F, out);
}